// round 16
// baseline (speedup 1.0000x reference)
#include <cuda_runtime.h>
#include <cstdint>

#define M_TOTAL 16384
#define K_DIM   2048
#define E_DIM   64
#define TOPK    8

// Chunked GEMM: each CTA computes a 32-row x 32-expert patch over full K.
#define BMs   32
#define BEs   32
#define BKs   32
#define NTILE (K_DIM / BKs)      // 64
#define ASTRs 36                 // a row stride: 32 k + 4 pad (16B-aligned, conflict-free)
#define ABUF  (BMs * ASTRs)      // 1152 floats
#define BBUF  (BKs * BEs)        // 1024 floats
#define BUFS  (ABUF + BBUF)      // 2176 floats per buffer (8.7 KB); x2 = 17.4 KB

// One-time W transpose scratch: Wt[k][e]
__device__ float Wt_g[(size_t)K_DIM * E_DIM];

__global__ void transpose_w(const float* __restrict__ W, float* __restrict__ Wt) {
    int t = blockIdx.x * blockDim.x + threadIdx.x;   // 131072
    int e = t >> 11;
    int k = t & (K_DIM - 1);
    Wt[(size_t)k * E_DIM + e] = W[(size_t)e * K_DIM + k];
}

// Packed fp32x2 FMA; per-lane rounding identical to scalar fmaf.
__device__ __forceinline__ float2 ffma2(float2 a, float2 b, float2 c) {
    float2 d;
    asm("fma.rn.f32x2 %0, %1, %2, %3;"
        : "=l"(reinterpret_cast<unsigned long long&>(d))
        : "l"(reinterpret_cast<unsigned long long&>(a)),
          "l"(reinterpret_cast<unsigned long long&>(b)),
          "l"(reinterpret_cast<unsigned long long&>(c)));
    return d;
}

__device__ __forceinline__ void cp_async16(uint32_t dst_smem, const void* src) {
    asm volatile("cp.async.ca.shared.global [%0], [%1], 16;"
                 :: "r"(dst_smem), "l"(src));
}
__device__ __forceinline__ void cp_async_commit() {
    asm volatile("cp.async.commit_group;");
}
__device__ __forceinline__ void cp_async_wait0() {
    asm volatile("cp.async.wait_group 0;");
}

// Chunked logits GEMM: grid = 1024 CTAs (512 m-strips x 2 e-halves), 64 thr.
// 1024/148 = 6.92 -> all resident, max 7 chunks/SM (7168 row-exp vs 8192 at
// grid 128): uses all 148 SMs. Warp = 16 experts (uniform LDS.128 b) x 1 row
// per lane (m-major a, LDS.128 per 4 k). Sequential ascending-k FMA chain per
// (m,e) -> logits bit-identical to all passing rounds.
__global__ __launch_bounds__(64, 1)
void router_gemm(const float* __restrict__ X, const float* __restrict__ Wt,
                 float* __restrict__ logits) {
    __shared__ float smem[2 * BUFS];           // 17.4 KB static

    const int tid    = threadIdx.x;
    const int w      = tid >> 5;               // 0..1
    const int lane   = tid & 31;
    const int bid    = blockIdx.x;
    const int e_base = (bid & 1) * BEs;        // 0 or 32 (global expert base)
    const int m0     = (bid >> 1) * BMs;       // m-strip
    const int eloc   = w * 16;                 // warp's local expert offset

    const uint32_t smem_u32 = (uint32_t)__cvta_generic_to_shared(smem);

    float2 acc[8];
    #pragma unroll
    for (int j = 0; j < 8; j++) acc[j] = make_float2(0.f, 0.f);

    // staging maps: 256 float4 per tile for a and for b -> 4 per thread.
    int ar[4], aq[4];
    #pragma unroll
    for (int i = 0; i < 4; i++) { int f = tid + i * 64; ar[i] = f >> 3; aq[i] = f & 7; }

    const float* xbase = &X[(size_t)m0 * K_DIM];

    // ---- preload tile 0 ----
    {
        uint32_t b0 = smem_u32 + (uint32_t)ABUF * 4u;
        #pragma unroll
        for (int i = 0; i < 4; i++) {
            int f = tid + i * 64;
            int bk = f >> 3, be4 = f & 7;
            cp_async16(b0 + (uint32_t)f * 16u,
                       &Wt[(size_t)bk * E_DIM + e_base + be4 * 4]);
        }
        cp_async_commit();
        #pragma unroll
        for (int i = 0; i < 4; i++) {
            float4 v = *reinterpret_cast<const float4*>(
                &xbase[(size_t)ar[i] * K_DIM + aq[i] * 4]);
            *reinterpret_cast<float4*>(&smem[ar[i] * ASTRs + aq[i] * 4]) = v;
        }
        cp_async_wait0();
    }
    __syncthreads();

    for (int t = 0; t < NTILE; t++) {
        const int cur = t & 1;
        const float* a_sm = smem + cur * BUFS;
        const float* b_sm = a_sm + ABUF;
        float* a_nx = smem + (cur ^ 1) * BUFS;

        const bool has_next = (t + 1 < NTILE);
        float4 pa[4];

        if (has_next) {
            int kn = (t + 1) * BKs;
            uint32_t bdst = smem_u32 + (uint32_t)((cur ^ 1) * BUFS + ABUF) * 4u;
            #pragma unroll
            for (int i = 0; i < 4; i++) {
                int f = tid + i * 64;
                int bk = f >> 3, be4 = f & 7;
                cp_async16(bdst + (uint32_t)f * 16u,
                           &Wt[(size_t)(kn + bk) * E_DIM + e_base + be4 * 4]);
            }
            cp_async_commit();
            #pragma unroll
            for (int i = 0; i < 4; i++)
                pa[i] = *reinterpret_cast<const float4*>(
                    &xbase[(size_t)ar[i] * K_DIM + kn + aq[i] * 4]);
        }

        // ---- mainloop: 8 k-quads of 4 ----
        #pragma unroll
        for (int kq = 0; kq < 8; kq++) {
            float4 av = *reinterpret_cast<const float4*>(&a_sm[lane * ASTRs + kq * 4]);
            float as[4] = {av.x, av.y, av.z, av.w};
            #pragma unroll
            for (int u = 0; u < 4; u++) {
                const int kk = kq * 4 + u;
                float4 b4[4];
                #pragma unroll
                for (int j = 0; j < 4; j++)
                    b4[j] = *reinterpret_cast<const float4*>(&b_sm[kk * BEs + eloc + 4 * j]);
                float2 ap = make_float2(as[u], as[u]);
                #pragma unroll
                for (int j = 0; j < 4; j++) {
                    float2 blo = make_float2(b4[j].x, b4[j].y);
                    float2 bhi = make_float2(b4[j].z, b4[j].w);
                    acc[2 * j]     = ffma2(ap, blo, acc[2 * j]);
                    acc[2 * j + 1] = ffma2(ap, bhi, acc[2 * j + 1]);
                }
            }
        }

        if (has_next) {
            #pragma unroll
            for (int i = 0; i < 4; i++)
                *reinterpret_cast<float4*>(&a_nx[ar[i] * ASTRs + aq[i] * 4]) = pa[i];
            cp_async_wait0();
        }
        __syncthreads();
    }

    // ---- epilogue: write 32x32 patch ----
    {
        const int m = m0 + lane;
        float* dst = &logits[(size_t)m * E_DIM + e_base + eloc];
        #pragma unroll
        for (int j = 0; j < 4; j++) {
            float4 v = make_float4(acc[2 * j].x, acc[2 * j].y,
                                   acc[2 * j + 1].x, acc[2 * j + 1].y);
            *reinterpret_cast<float4*>(&dst[4 * j]) = v;
        }
    }
}

// Per-token top-8 (strict >: ties keep earlier index, matching jax top_k)
// + fp32 softmax. Verbatim from the round-2 passing kernel.
__global__ void topk_softmax(const float* __restrict__ logits,
                             float* __restrict__ wout,
                             float* __restrict__ eout) {
    int t = blockIdx.x * blockDim.x + threadIdx.x;
    if (t >= M_TOTAL) return;

    const float4* row = reinterpret_cast<const float4*>(logits + (size_t)t * E_DIM);

    float tv[TOPK];
    int   ti[TOPK];
    #pragma unroll
    for (int i = 0; i < TOPK; i++) { tv[i] = -3.4e38f; ti[i] = 0; }

    #pragma unroll
    for (int q = 0; q < E_DIM / 4; q++) {
        float4 v4 = row[q];
        float vs[4] = {v4.x, v4.y, v4.z, v4.w};
        #pragma unroll
        for (int u = 0; u < 4; u++) {
            float v = vs[u];
            int   e = q * 4 + u;
            if (v > tv[TOPK - 1]) {
                tv[TOPK - 1] = v; ti[TOPK - 1] = e;
                #pragma unroll
                for (int j = TOPK - 1; j > 0; j--) {
                    if (tv[j] > tv[j - 1]) {
                        float tf = tv[j]; tv[j] = tv[j - 1]; tv[j - 1] = tf;
                        int   tx = ti[j]; ti[j] = ti[j - 1]; ti[j - 1] = tx;
                    }
                }
            }
        }
    }

    float m = tv[0];
    float ev[TOPK];
    float s = 0.f;
    #pragma unroll
    for (int i = 0; i < TOPK; i++) { ev[i] = __expf(tv[i] - m); s += ev[i]; }
    float inv = 1.f / s;
    #pragma unroll
    for (int i = 0; i < TOPK; i++) {
        wout[(size_t)t * TOPK + i] = ev[i] * inv;
        eout[(size_t)t * TOPK + i] = (float)ti[i];
    }
}

extern "C" void kernel_launch(void* const* d_in, const int* in_sizes, int n_in,
                              void* d_out, int out_size) {
    const float* X = (const float*)d_in[0];   // [4,4096,2048] fp32
    const float* W = (const float*)d_in[1];   // [64,2048]     fp32

    float* out    = (float*)d_out;
    float* logits = out;                                   // 16384*64
    float* wts    = out + (size_t)M_TOTAL * E_DIM;         // 16384*8
    float* exps   = wts + (size_t)M_TOTAL * TOPK;          // 16384*8

    float* Wt;
    cudaGetSymbolAddress((void**)&Wt, Wt_g);

    transpose_w<<<(K_DIM * E_DIM) / 256, 256>>>(W, Wt);
    router_gemm<<<(M_TOTAL / BMs) * (E_DIM / BEs), 64>>>(X, Wt, logits);
    topk_softmax<<<(M_TOTAL + 255) / 256, 256>>>(logits, wts, exps);
}

// round 17
// speedup vs baseline: 1.7947x; 1.7947x over previous
#include <cuda_runtime.h>
#include <cstdint>

#define M_TOTAL 16384
#define K_DIM   2048
#define E_DIM   64
#define TOPK    8

#define BM    128
#define BK    64
#define NTILE (K_DIM / BK)   // 32
#define NTHR  256
#define ASTR  68             // a_sm row stride (floats): 64 data + 4 pad; 16B-aligned,
                             // STS.128 / LDS.128 both conflict-free
#define BUFSZ (BM * ASTR + BK * E_DIM)   // 12800 floats per buffer (51.2 KB)

// One-time W transpose scratch: Wt[k][e]
__device__ float Wt_g[(size_t)K_DIM * E_DIM];

// Tiled 32x32 smem transpose: coalesced reads along k AND coalesced writes
// along e (the old version's scattered 4B writes cost 5.0 us; this is ~1 us).
__global__ void transpose_w(const float* __restrict__ W, float* __restrict__ Wt) {
    __shared__ float tile[32][33];
    const int kt = blockIdx.x >> 1;        // k-tile 0..63
    const int et = blockIdx.x & 1;         // e-tile 0..1
    const int x  = threadIdx.x & 31;
    const int y  = threadIdx.x >> 5;       // 0..7
    const int k0 = kt * 32, e0 = et * 32;

    #pragma unroll
    for (int j = 0; j < 4; j++) {
        int e = y + 8 * j;
        tile[e][x] = W[(size_t)(e0 + e) * K_DIM + k0 + x];   // coalesced along k
    }
    __syncthreads();
    #pragma unroll
    for (int j = 0; j < 4; j++) {
        int k = y + 8 * j;
        Wt[(size_t)(k0 + k) * E_DIM + e0 + x] = tile[x][k];  // coalesced along e
    }
}

// Packed fp32x2 FMA; per-lane rounding identical to scalar fmaf.
__device__ __forceinline__ float2 ffma2(float2 a, float2 b, float2 c) {
    float2 d;
    asm("fma.rn.f32x2 %0, %1, %2, %3;"
        : "=l"(reinterpret_cast<unsigned long long&>(d))
        : "l"(reinterpret_cast<unsigned long long&>(a)),
          "l"(reinterpret_cast<unsigned long long&>(b)),
          "l"(reinterpret_cast<unsigned long long&>(c)));
    return d;
}

__device__ __forceinline__ void cp_async16(uint32_t dst_smem, const void* src) {
    asm volatile("cp.async.ca.shared.global [%0], [%1], 16;"
                 :: "r"(dst_smem), "l"(src));
}
__device__ __forceinline__ void cp_async_commit() {
    asm volatile("cp.async.commit_group;");
}
__device__ __forceinline__ void cp_async_wait0() {
    asm volatile("cp.async.wait_group 0;");
}

// Fused logits GEMM + top-8 + softmax. Round-15 winner verbatim (best
// measured, 115.0 us): BK=64 double buffer, m-major a (stride 68, STS.128
// staging, LDS.128 per 4 k), k-major b via cp.async with uniform LDS.128,
// warp = 16 experts x 2 m-rows. Sequential ascending-k FMA chain per (m,e)
// -> bit-identical outputs (index exactness is mandatory).
__global__ __launch_bounds__(NTHR, 1)
void router_fused(const float* __restrict__ X, const float* __restrict__ Wt,
                  float* __restrict__ logits,
                  float* __restrict__ wout, float* __restrict__ eout) {
    extern __shared__ float smem[];            // 2 * BUFSZ floats = 102.4 KB

    const int tid  = threadIdx.x;
    const int w    = tid >> 5;
    const int lane = tid & 31;
    const int e0   = (w & 3) * 16;
    const int m1   = (w >> 2) * 64 + lane;
    const int m2   = m1 + 32;
    const int m0   = blockIdx.x * BM;

    const uint32_t smem_u32 = (uint32_t)__cvta_generic_to_shared(smem);

    float2 acc[2][8];
    #pragma unroll
    for (int r = 0; r < 2; r++)
        #pragma unroll
        for (int j = 0; j < 8; j++) acc[r][j] = make_float2(0.f, 0.f);

    int arow[8], aq[8];
    #pragma unroll
    for (int i = 0; i < 8; i++) { int f = tid + i * NTHR; arow[i] = f >> 4; aq[i] = f & 15; }

    // ---- preload tile 0 ----
    {
        uint32_t b0 = smem_u32 + (uint32_t)(BM * ASTR) * 4u;
        #pragma unroll
        for (int i = 0; i < 4; i++)
            cp_async16(b0 + (tid + i * NTHR) * 16u, &Wt[(size_t)(tid + i * NTHR) * 4]);
        cp_async_commit();
        #pragma unroll
        for (int i = 0; i < 8; i++) {
            float4 v = *reinterpret_cast<const float4*>(
                &X[(size_t)(m0 + arow[i]) * K_DIM + aq[i] * 4]);
            *reinterpret_cast<float4*>(&smem[arow[i] * ASTR + aq[i] * 4]) = v;
        }
        cp_async_wait0();
    }
    __syncthreads();

    for (int t = 0; t < NTILE; t++) {
        const int cur = t & 1;
        const float* a_sm = smem + cur * BUFSZ;
        const float* b_sm = a_sm + BM * ASTR;
        float* a_nx = smem + (cur ^ 1) * BUFSZ;

        const bool has_next = (t + 1 < NTILE);
        float4 pa[4];

        if (has_next) {
            int kn = (t + 1) * BK;
            uint32_t bdst = smem_u32 + (uint32_t)((cur ^ 1) * BUFSZ + BM * ASTR) * 4u;
            const float* bsrc = &Wt[(size_t)kn * E_DIM];
            #pragma unroll
            for (int i = 0; i < 4; i++)
                cp_async16(bdst + (tid + i * NTHR) * 16u, bsrc + (size_t)(tid + i * NTHR) * 4);
            cp_async_commit();
            #pragma unroll
            for (int i = 0; i < 4; i++)
                pa[i] = *reinterpret_cast<const float4*>(
                    &X[(size_t)(m0 + arow[i]) * K_DIM + kn + aq[i] * 4]);
        }

        // ---- first half: k-quads 0..7 ----
        #pragma unroll
        for (int kq = 0; kq < 8; kq++) {
            float4 a1v = *reinterpret_cast<const float4*>(&a_sm[m1 * ASTR + kq * 4]);
            float4 a2v = *reinterpret_cast<const float4*>(&a_sm[m2 * ASTR + kq * 4]);
            float a1s[4] = {a1v.x, a1v.y, a1v.z, a1v.w};
            float a2s[4] = {a2v.x, a2v.y, a2v.z, a2v.w};
            #pragma unroll
            for (int u = 0; u < 4; u++) {
                const int kk = kq * 4 + u;
                float4 b4[4];
                #pragma unroll
                for (int j = 0; j < 4; j++)
                    b4[j] = *reinterpret_cast<const float4*>(&b_sm[kk * E_DIM + e0 + 4 * j]);
                float2 ap1 = make_float2(a1s[u], a1s[u]);
                float2 ap2 = make_float2(a2s[u], a2s[u]);
                #pragma unroll
                for (int j = 0; j < 4; j++) {
                    float2 blo = make_float2(b4[j].x, b4[j].y);
                    float2 bhi = make_float2(b4[j].z, b4[j].w);
                    acc[0][2 * j]     = ffma2(ap1, blo, acc[0][2 * j]);
                    acc[0][2 * j + 1] = ffma2(ap1, bhi, acc[0][2 * j + 1]);
                    acc[1][2 * j]     = ffma2(ap2, blo, acc[1][2 * j]);
                    acc[1][2 * j + 1] = ffma2(ap2, bhi, acc[1][2 * j + 1]);
                }
            }
        }

        // stage a batch 1 (4 STS.128), issue a batch 2
        if (has_next) {
            int kn = (t + 1) * BK;
            #pragma unroll
            for (int i = 0; i < 4; i++)
                *reinterpret_cast<float4*>(&a_nx[arow[i] * ASTR + aq[i] * 4]) = pa[i];
            #pragma unroll
            for (int i = 0; i < 4; i++)
                pa[i] = *reinterpret_cast<const float4*>(
                    &X[(size_t)(m0 + arow[i + 4]) * K_DIM + kn + aq[i + 4] * 4]);
        }

        // ---- second half: k-quads 8..15 ----
        #pragma unroll
        for (int kq = 8; kq < 16; kq++) {
            float4 a1v = *reinterpret_cast<const float4*>(&a_sm[m1 * ASTR + kq * 4]);
            float4 a2v = *reinterpret_cast<const float4*>(&a_sm[m2 * ASTR + kq * 4]);
            float a1s[4] = {a1v.x, a1v.y, a1v.z, a1v.w};
            float a2s[4] = {a2v.x, a2v.y, a2v.z, a2v.w};
            #pragma unroll
            for (int u = 0; u < 4; u++) {
                const int kk = kq * 4 + u;
                float4 b4[4];
                #pragma unroll
                for (int j = 0; j < 4; j++)
                    b4[j] = *reinterpret_cast<const float4*>(&b_sm[kk * E_DIM + e0 + 4 * j]);
                float2 ap1 = make_float2(a1s[u], a1s[u]);
                float2 ap2 = make_float2(a2s[u], a2s[u]);
                #pragma unroll
                for (int j = 0; j < 4; j++) {
                    float2 blo = make_float2(b4[j].x, b4[j].y);
                    float2 bhi = make_float2(b4[j].z, b4[j].w);
                    acc[0][2 * j]     = ffma2(ap1, blo, acc[0][2 * j]);
                    acc[0][2 * j + 1] = ffma2(ap1, bhi, acc[0][2 * j + 1]);
                    acc[1][2 * j]     = ffma2(ap2, blo, acc[1][2 * j]);
                    acc[1][2 * j + 1] = ffma2(ap2, bhi, acc[1][2 * j + 1]);
                }
            }
        }

        // stage a batch 2, wait for b
        if (has_next) {
            #pragma unroll
            for (int i = 0; i < 4; i++)
                *reinterpret_cast<float4*>(&a_nx[arow[i + 4] * ASTR + aq[i + 4] * 4]) = pa[i];
            cp_async_wait0();
        }
        __syncthreads();
    }

    // ---- epilogue: logits to global + stage rows in smem for topk ----
    #pragma unroll
    for (int r = 0; r < 2; r++) {
        int m = r ? m2 : m1;
        #pragma unroll
        for (int j = 0; j < 4; j++) {
            float4 v = make_float4(acc[r][2 * j].x, acc[r][2 * j].y,
                                   acc[r][2 * j + 1].x, acc[r][2 * j + 1].y);
            *reinterpret_cast<float4*>(&logits[(size_t)(m0 + m) * E_DIM + e0 + 4 * j]) = v;
            *reinterpret_cast<float4*>(&smem[m * ASTR + e0 + 4 * j]) = v;
        }
    }
    __syncthreads();

    // ---- top-8 + softmax: one thread per token (threads 0..127) ----
    if (tid < BM) {
        const float* row = &smem[tid * ASTR];
        float tv[TOPK];
        int   ti[TOPK];
        #pragma unroll
        for (int i = 0; i < TOPK; i++) { tv[i] = -3.4e38f; ti[i] = 0; }

        #pragma unroll
        for (int q = 0; q < E_DIM / 4; q++) {
            float4 v4 = *reinterpret_cast<const float4*>(&row[q * 4]);
            float vs[4] = {v4.x, v4.y, v4.z, v4.w};
            #pragma unroll
            for (int u = 0; u < 4; u++) {
                float v = vs[u];
                int   e = q * 4 + u;
                if (v > tv[TOPK - 1]) {
                    tv[TOPK - 1] = v; ti[TOPK - 1] = e;
                    #pragma unroll
                    for (int j = TOPK - 1; j > 0; j--) {
                        if (tv[j] > tv[j - 1]) {   // strict: ties keep earlier index
                            float tf = tv[j]; tv[j] = tv[j - 1]; tv[j - 1] = tf;
                            int   tx = ti[j]; ti[j] = ti[j - 1]; ti[j - 1] = tx;
                        }
                    }
                }
            }
        }

        float mx = tv[0];
        float ev[TOPK], ssum = 0.f;
        #pragma unroll
        for (int i = 0; i < TOPK; i++) { ev[i] = __expf(tv[i] - mx); ssum += ev[i]; }
        float inv = 1.f / ssum;
        size_t tok = (size_t)(m0 + tid);
        #pragma unroll
        for (int i = 0; i < TOPK; i++) {
            wout[tok * TOPK + i] = ev[i] * inv;
            eout[tok * TOPK + i] = (float)ti[i];
        }
    }
}

extern "C" void kernel_launch(void* const* d_in, const int* in_sizes, int n_in,
                              void* d_out, int out_size) {
    const float* X = (const float*)d_in[0];   // [4,4096,2048] fp32
    const float* W = (const float*)d_in[1];   // [64,2048]     fp32

    float* out    = (float*)d_out;
    float* logits = out;                                   // 16384*64
    float* wts    = out + (size_t)M_TOTAL * E_DIM;         // 16384*8
    float* exps   = wts + (size_t)M_TOTAL * TOPK;          // 16384*8

    float* Wt;
    cudaGetSymbolAddress((void**)&Wt, Wt_g);

    const int smem_bytes = 2 * BUFSZ * (int)sizeof(float);   // 102400 B
    cudaFuncSetAttribute(router_fused, cudaFuncAttributeMaxDynamicSharedMemorySize,
                         smem_bytes);

    transpose_w<<<(K_DIM / 32) * (E_DIM / 32), 256>>>(W, Wt);
    router_fused<<<M_TOTAL / BM, NTHR, smem_bytes>>>(X, Wt, logits, wts, exps);
}